// round 16
// baseline (speedup 1.0000x reference)
#include <cuda_runtime.h>
#include <math.h>
#include <stdint.h>

// ---------------------------------------------------------------------------
// Problem constants
// ---------------------------------------------------------------------------
namespace {
constexpr int NB = 8, NN = 64, RRI = 2048;
constexpr int DIM = 4096, HD = 512, NO = 151, NRC = 51, TSTEP = 3;
constexpr int NOBJ = NB * NN;    // 512
constexpr int NREL = NB * RRI;   // 16384

// scratch offsets (floats)
constexpr size_t OFF_XO     = 0;
constexpr size_t OFF_HO     = OFF_XO     + (size_t)NOBJ * HD;
constexpr size_t OFF_XR     = OFF_HO     + (size_t)NOBJ * HD;
constexpr size_t OFF_HR     = OFF_XR     + (size_t)NREL * HD;
constexpr size_t OFF_GSO    = OFF_HR     + (size_t)NREL * HD;      // 512x3072
constexpr size_t OFF_SO     = OFF_GSO    + (size_t)NOBJ * 6 * HD;  // 512x1024
constexpr size_t OFF_MO     = OFF_SO     + (size_t)NOBJ * 2 * HD;  // 512x512
constexpr size_t OFF_RHO    = OFF_MO     + (size_t)NOBJ * HD;      // 512x512
constexpr size_t OFF_AZROBJ = OFF_RHO    + (size_t)NOBJ * HD;      // 512x1024
constexpr size_t OFF_AHOBJ  = OFF_AZROBJ + (size_t)NOBJ * 2 * HD;  // 512x512
constexpr size_t OFF_ZOBJ   = OFF_AHOBJ  + (size_t)NOBJ * HD;      // 512x512
constexpr size_t OFF_AZR    = OFF_ZOBJ   + (size_t)NOBJ * HD;      // 16384x1024
constexpr size_t OFF_Z      = OFF_AZR    + (size_t)NREL * 2 * HD;
constexpr size_t OFF_RH     = OFF_Z      + (size_t)NREL * HD;
constexpr size_t OFF_AH     = OFF_RH     + (size_t)NREL * HD;
constexpr size_t OFF_TREL   = OFF_AH     + (size_t)NREL * HD;
constexpr size_t OFF_TOBJ   = OFF_TREL   + (size_t)NREL * HD;
constexpr size_t OFF_PROBS  = OFF_TOBJ   + (size_t)NOBJ * HD;      // 512x151
// transposed / padded weights ([N,K] row-major for the GEMM's B operand)
constexpr size_t OFF_PSPOT  = OFF_PROBS  + (size_t)NOBJ * NO;      // 3072x512
constexpr size_t OFF_WZRHT  = OFF_PSPOT  + (size_t)6 * HD * HD;    // 1536x512
constexpr size_t OFF_UZRT   = OFF_WZRHT  + (size_t)3 * HD * HD;    // 1024x512
constexpr size_t OFF_UHT    = OFF_UZRT   + (size_t)2 * HD * HD;    // 512x512
constexpr size_t OFF_WRSROT = OFF_UHT    + (size_t)HD * HD;        // 512x1024
constexpr size_t OFF_WZROT  = OFF_WRSROT + (size_t)HD * 2 * HD;    // 1024x1024
constexpr size_t OFF_WHOT   = OFF_WZROT  + (size_t)2 * HD * 2 * HD;// 512x1024
constexpr size_t OFF_WRELT  = OFF_WHOT   + (size_t)HD * 2 * HD;    // 512x4096
constexpr size_t OFF_WOBJT  = OFF_WRELT  + (size_t)HD * DIM;       // 512x4096
constexpr size_t OFF_WORT   = OFF_WOBJT  + (size_t)HD * DIM;       // 512x1024
constexpr size_t OFF_WOBT   = OFF_WORT   + (size_t)HD * 2 * HD;    // 512x1024
constexpr size_t OFF_WCRT   = OFF_WOBT   + (size_t)HD * 2 * HD;    // 128x512
constexpr size_t OFF_WCOT   = OFF_WCRT   + (size_t)128 * HD;       // 256x512
constexpr size_t OFF_RC     = OFF_WCOT   + (size_t)256 * HD;       // 16384x128
constexpr size_t OFF_OC     = OFF_RC     + (size_t)NREL * 128;     // 512x256
constexpr size_t SCRATCH_FLOATS = OFF_OC + (size_t)NOBJ * 256 + 1024;

// output offsets (floats), tuple order of the reference return
constexpr size_t O_OBJREF = 0;                                  // 512*151
constexpr size_t O_PREDS  = O_OBJREF + (size_t)NOBJ * NO;       // 512
constexpr size_t O_RELL   = O_PREDS  + (size_t)NOBJ;            // 16384*51
constexpr size_t O_SCP    = O_RELL   + (size_t)NREL * NRC;      // 16384*51
constexpr size_t O_SCENT  = O_SCP    + (size_t)NREL * NRC;      // 512*151
}

__device__ float g_scratch[SCRATCH_FLOATS];

// CSR for scatter->gather conversion (built once per launch, DETERMINISTIC)
__device__ int g_cnt[2 * NOBJ];
__device__ int g_off[2 * NOBJ + 1];
__device__ int g_list[2 * NREL];

__device__ __forceinline__ float sigm(float x) { return 1.f / (1.f + expf(-x)); }

// ---------------------------------------------------------------------------
// FP16 tensor-core GEMM (mma.sync.m16n8k16, fp32 accum), fragment-major SMEM,
// double-buffered (single sync/chunk). Templated on NW = warps along N.
// BN = 64*NW, threads = 64*NW (warp grid 2 x NW), warp tile ALWAYS 64x64 —
// the measured-optimal tile (tensor util tracks LDS/mma: 0.375 here).
// Prefetch staged as packed half2 (same cvt.rn on the same values ->
// bit-identical; validated round 15) to relieve the 255-reg cap.
// Per-output-element K accumulation order IDENTICAL for all NW (numerics
// frozen to the validated round-6/9/10 path; only M/N tiling varies).
// C[M,N] (= or +=) [A | A2][M,K] @ BT[N,K]^T (+bias)(tanh), optional dual out.
// ---------------------------------------------------------------------------
__device__ __forceinline__ unsigned pack_h2(float x, float y) {
    unsigned u;
    asm("{ .reg .f16 lo, hi;\n\t"
        "cvt.rn.f16.f32 lo, %1; cvt.rn.f16.f32 hi, %2;\n\t"
        "mov.b32 %0, {lo, hi}; }"
        : "=r"(u) : "f"(x), "f"(y));
    return u;
}

constexpr int A_FRAG_STRIDE = 132;
constexpr int B_FRAG_STRIDE = 66;
constexpr int A_REGION_U32  = 16 * A_FRAG_STRIDE;   // 2112 (BM=128 always)

template<int NW>
struct MMCfg {
    static constexpr int THREADS = 64 * NW;
    static constexpr int BN      = 64 * NW;
    static constexpr int B_REGION_U32 = 16 * NW * B_FRAG_STRIDE;
    static constexpr int BUF_U32 = A_REGION_U32 + B_REGION_U32;
    static constexpr int SMEM    = 2 * BUF_U32 * 4;
    static constexpr int IA      = 16 / NW;   // A float4 loads per thread
};

template<int NW>
__global__ void __launch_bounds__(64 * NW)
mm_f16(int M, int N, int K,
       const float* __restrict__ A, const float* __restrict__ A2,
       int kSplit, int lda,
       const float* __restrict__ BT, int ldb,
       float* __restrict__ C, float* __restrict__ C2, int ldc,
       const float* __restrict__ bias, int accFlag, int act)
{
    using Cfg = MMCfg<NW>;
    extern __shared__ unsigned smv[];
    const int tid  = threadIdx.x;
    const int lane = tid & 31;
    const int warp = tid >> 5;
    const int wm   = warp / NW;     // 0..1
    const int wn   = warp % NW;     // 0..NW-1
    const int m0   = blockIdx.y * 128;
    const int n0   = blockIdx.x * Cfg::BN;

    float acc[4][8][4];
#pragma unroll
    for (int mf = 0; mf < 4; mf++)
#pragma unroll
        for (int nf = 0; nf < 8; nf++)
#pragma unroll
            for (int i = 0; i < 4; i++) acc[mf][nf][i] = 0.f;

    unsigned uA[2 * Cfg::IA], uB[16];   // packed half2 prefetch

    auto ldgA = [&](int c) {
        int k0 = c * 32;
        const float* Ap = A;
        if (kSplit && k0 >= kSplit) { Ap = A2; k0 -= kSplit; }
#pragma unroll
        for (int i = 0; i < Cfg::IA; i++) {
            int idx = tid + i * Cfg::THREADS;
            int row = idx >> 3, cc = (idx & 7) << 2;
            float4 v = *reinterpret_cast<const float4*>(
                &Ap[(size_t)(m0 + row) * lda + k0 + cc]);
            uA[i * 2]     = pack_h2(v.x, v.y);
            uA[i * 2 + 1] = pack_h2(v.z, v.w);
        }
    };
    auto ldgB = [&](int c) {
        int k0 = c * 32;
#pragma unroll
        for (int i = 0; i < 8; i++) {
            int idx = tid + i * Cfg::THREADS;
            int row = idx >> 3, cc = (idx & 7) << 2;
            float4 v = *reinterpret_cast<const float4*>(
                &BT[(size_t)(n0 + row) * ldb + k0 + cc]);
            uB[i * 2]     = pack_h2(v.x, v.y);
            uB[i * 2 + 1] = pack_h2(v.z, v.w);
        }
    };
    auto sts = [&](int b) {
        unsigned* Ab = &smv[b * Cfg::BUF_U32];
        unsigned* Bb = Ab + A_REGION_U32;
#pragma unroll
        for (int i = 0; i < Cfg::IA; i++) {
            int idx = tid + i * Cfg::THREADS;
            int row = idx >> 3, c0 = (idx & 7) << 2;
            int kb  = (c0 >> 4) & 1;
            int f   = ((row >> 4) << 1) | kb;
            int r   = ((row >> 3) & 1) | (((c0 >> 3) & 1) << 1);
            int tg0 = (c0 & 7) >> 1;                    // 0 or 2
            int lane0 = ((row & 7) << 2) | tg0;
            int base = f * A_FRAG_STRIDE + lane0 * 4 + r;
            Ab[base]     = uA[i * 2];
            Ab[base + 4] = uA[i * 2 + 1];
        }
#pragma unroll
        for (int i = 0; i < 8; i++) {
            int idx = tid + i * Cfg::THREADS;
            int n = idx >> 3, c0 = (idx & 7) << 2;
            int kb  = (c0 >> 4) & 1;
            int f   = ((n >> 3) << 1) | kb;
            int r   = (c0 >> 3) & 1;
            int tg0 = (c0 & 7) >> 1;
            int lane0 = ((n & 7) << 2) | tg0;
            int base = f * B_FRAG_STRIDE + lane0 * 2 + r;
            Bb[base]     = uB[i * 2];
            Bb[base + 2] = uB[i * 2 + 1];
        }
    };
    auto compute = [&](int b, int kbFrom, int kbTo) {
        const unsigned* Ab = &smv[b * Cfg::BUF_U32];
        const unsigned* Bb = Ab + A_REGION_U32;
#pragma unroll
        for (int kb = kbFrom; kb < kbTo; kb++) {
            uint4 a[4];
            uint2 bf[8];
#pragma unroll
            for (int mf = 0; mf < 4; mf++) {
                int f = ((wm * 4 + mf) << 1) | kb;
                a[mf] = *reinterpret_cast<const uint4*>(
                    &Ab[f * A_FRAG_STRIDE + lane * 4]);
            }
#pragma unroll
            for (int nf = 0; nf < 8; nf++) {
                int f = ((wn * 8 + nf) << 1) | kb;
                bf[nf] = *reinterpret_cast<const uint2*>(
                    &Bb[f * B_FRAG_STRIDE + lane * 2]);
            }
#pragma unroll
            for (int mf = 0; mf < 4; mf++)
#pragma unroll
                for (int nf = 0; nf < 8; nf++) {
                    asm volatile(
                        "mma.sync.aligned.m16n8k16.row.col.f32.f16.f16.f32 "
                        "{%0,%1,%2,%3},{%4,%5,%6,%7},{%8,%9},{%0,%1,%2,%3};"
                        : "+f"(acc[mf][nf][0]), "+f"(acc[mf][nf][1]),
                          "+f"(acc[mf][nf][2]), "+f"(acc[mf][nf][3])
                        : "r"(a[mf].x), "r"(a[mf].y), "r"(a[mf].z), "r"(a[mf].w),
                          "r"(bf[nf].x), "r"(bf[nf].y));
                }
        }
    };

    const int nc = K / 32;
    ldgA(0); ldgB(0);
    sts(0);
    __syncthreads();

    for (int c = 0; c < nc; c++) {
        const int b = c & 1;
        if (c + 1 < nc) ldgA(c + 1);
        compute(b, 0, 1);
        if (c + 1 < nc) ldgB(c + 1);
        compute(b, 1, 2);
        if (c + 1 < nc) {
            sts(1 - b);          // other buffer; its readers synced at c-1
            __syncthreads();     // single barrier per chunk
        }
    }

    // epilogue
    const int g  = lane >> 2;
    const int tg = lane & 3;
#pragma unroll
    for (int mf = 0; mf < 4; mf++) {
        const int r0 = m0 + wm * 64 + mf * 16 + g;
#pragma unroll
        for (int nf = 0; nf < 8; nf++) {
            const int c0 = n0 + wn * 64 + nf * 8 + tg * 2;
#pragma unroll
            for (int h = 0; h < 2; h++) {
                const int row = r0 + h * 8;
                float vx = acc[mf][nf][2 * h + 0];
                float vy = acc[mf][nf][2 * h + 1];
                size_t off = (size_t)row * ldc + c0;
                if (accFlag) {
                    float2 o = *reinterpret_cast<const float2*>(&C[off]);
                    vx += o.x; vy += o.y;
                }
                if (bias) { vx += bias[c0]; vy += bias[c0 + 1]; }
                if (act == 1) { vx = tanhf(vx); vy = tanhf(vy); }
                float2 o2; o2.x = vx; o2.y = vy;
                *reinterpret_cast<float2*>(&C[off]) = o2;
                if (C2) *reinterpret_cast<float2*>(&C2[off]) = o2;
            }
        }
    }
}

// ---------------------------------------------------------------------------
// FP32 tiled SGEMM (only for ragged-K probs @ W_prob), optional dual-write
// ---------------------------------------------------------------------------
__global__ void sgemm_gk(int M, int N, int K,
                         const float* __restrict__ A, int lda,
                         const float* __restrict__ B, int ldb,
                         float* __restrict__ C, float* __restrict__ C2, int ldc,
                         const float* __restrict__ bias, int accFlag)
{
    constexpr int BM = 64, BN = 64, BK = 16, TM = 4, TN = 4;
    constexpr int TX = BN / TN;
    __shared__ float As[BK][BM];
    __shared__ float Bs[BK][BN];
    const int tid = threadIdx.x;
    const int tr = tid / TX, tc = tid % TX;
    const int rowBase = blockIdx.y * BM, colBase = blockIdx.x * BN;
    float acc[TM][TN];
#pragma unroll
    for (int i = 0; i < TM; i++)
#pragma unroll
        for (int j = 0; j < TN; j++) acc[i][j] = 0.f;
    const int arow = tid / (BK / 4), acol = (tid % (BK / 4)) * 4;
    const int brow = tid / (BN / 4), bcol = (tid % (BN / 4)) * 4;
    for (int k0 = 0; k0 < K; k0 += BK) {
#pragma unroll
        for (int j = 0; j < 4; j++) {
            int gk = k0 + acol + j;
            As[acol + j][arow] = (gk < K) ? A[(size_t)(rowBase + arow) * lda + gk] : 0.f;
        }
#pragma unroll
        for (int j = 0; j < 4; j++) {
            int gk = k0 + brow;
            Bs[brow][bcol + j] = (gk < K) ? B[(size_t)gk * ldb + colBase + bcol + j] : 0.f;
        }
        __syncthreads();
#pragma unroll
        for (int kk = 0; kk < BK; kk++) {
            float ra[TM], rb[TN];
#pragma unroll
            for (int i = 0; i < TM; i++) ra[i] = As[kk][tr * TM + i];
#pragma unroll
            for (int j = 0; j < TN; j++) rb[j] = Bs[kk][tc * TN + j];
#pragma unroll
            for (int i = 0; i < TM; i++)
#pragma unroll
                for (int j = 0; j < TN; j++) acc[i][j] += ra[i] * rb[j];
        }
        __syncthreads();
    }
#pragma unroll
    for (int i = 0; i < TM; i++) {
        int gr = rowBase + tr * TM + i;
#pragma unroll
        for (int j = 0; j < TN; j++) {
            int gc = colBase + tc * TN + j;
            float v = acc[i][j];
            size_t off = (size_t)gr * ldc + gc;
            if (accFlag) v += C[off];
            if (bias) v += bias[gc];
            C[off] = v;
            if (C2) C2[off] = v;
        }
    }
}

// ---------------------------------------------------------------------------
// Batched transpose: all weight transposes in ONE launch.
// ---------------------------------------------------------------------------
struct TJob { const float* src; float* dst; int R, C, lds, ldd, tileStart; };
struct TJobs { TJob j[20]; int njobs; };

__global__ void k_transpose_b(TJobs jobs)
{
    __shared__ float t[32][33];
    const int bid = blockIdx.x;
    int lo = 0;
#pragma unroll 1
    for (int k = 1; k < jobs.njobs; k++)
        if (jobs.j[k].tileStart <= bid) lo = k;
    const TJob jb = jobs.j[lo];
    const int lt = bid - jb.tileStart;
    const int tx_n = (jb.C + 31) >> 5;
    const int cb = (lt % tx_n) * 32;
    const int rb = (lt / tx_n) * 32;
    const int tx = threadIdx.x, ty = threadIdx.y;
#pragma unroll
    for (int i = 0; i < 4; i++) {
        int r = rb + ty + i * 8, c = cb + tx;
        if (r < jb.R && c < jb.C) t[ty + i * 8][tx] = jb.src[(size_t)r * jb.lds + c];
    }
    __syncthreads();
#pragma unroll
    for (int i = 0; i < 4; i++) {
        int c = cb + ty + i * 8, r = rb + tx;
        if (c < jb.C && r < jb.R) jb.dst[(size_t)c * jb.ldd + r] = t[tx][ty + i * 8];
    }
}

// ---------------------------------------------------------------------------
// Elementwise / utility kernels
// ---------------------------------------------------------------------------
__global__ void k_softmax(const float* __restrict__ in, float* __restrict__ out,
                          int rows, int cols)
{
    int row = blockIdx.x * blockDim.y + threadIdx.y;
    if (row >= rows) return;
    int lane = threadIdx.x;
    const float* r = in + (size_t)row * cols;
    float m = __int_as_float(0xff800000);
    for (int c = lane; c < cols; c += 32) m = fmaxf(m, r[c]);
    for (int o = 16; o; o >>= 1) m = fmaxf(m, __shfl_xor_sync(~0u, m, o));
    float s = 0.f;
    for (int c = lane; c < cols; c += 32) s += expf(r[c] - m);
    for (int o = 16; o; o >>= 1) s += __shfl_xor_sync(~0u, s, o);
    float inv = 1.f / s;
    float* w = out + (size_t)row * cols;
    for (int c = lane; c < cols; c += 32) w[c] = expf(r[c] - m) * inv;
}

// fused head: logits = in[:, :cols] + bias ; softmax ; optional argmax[1:]
__global__ void k_head(const float* __restrict__ in, int ldin,
                       const float* __restrict__ bias, int cols, int rows,
                       float* __restrict__ logits, float* __restrict__ sm,
                       float* __restrict__ preds)
{
    int row = blockIdx.x * blockDim.y + threadIdx.y;
    if (row >= rows) return;
    int lane = threadIdx.x;
    const float* r = in + (size_t)row * ldin;
    float m = __int_as_float(0xff800000);
    float bv = __int_as_float(0xff800000);
    int bi = cols;
    for (int c = lane; c < cols; c += 32) {
        float t = r[c] + bias[c];
        m = fmaxf(m, t);
        if (c >= 1 && (t > bv || (t == bv && c < bi))) { bv = t; bi = c; }
    }
    for (int o = 16; o; o >>= 1) m = fmaxf(m, __shfl_xor_sync(~0u, m, o));
    if (preds) {
        for (int o = 16; o; o >>= 1) {
            float ov = __shfl_xor_sync(~0u, bv, o);
            int oi = __shfl_xor_sync(~0u, bi, o);
            if (ov > bv || (ov == bv && oi < bi)) { bv = ov; bi = oi; }
        }
        if (lane == 0) preds[row] = (float)bi;
    }
    float s = 0.f;
    for (int c = lane; c < cols; c += 32) s += expf(r[c] + bias[c] - m);
    for (int o = 16; o; o >>= 1) s += __shfl_xor_sync(~0u, s, o);
    float inv = 1.f / s;
    for (int c = lane; c < cols; c += 32) {
        float t = r[c] + bias[c];
        logits[(size_t)row * cols + c] = t;
        sm[(size_t)row * cols + c] = expf(t - m) * inv;
    }
}

// --- CSR build (once per launch) ---
__global__ void k_count(const int* __restrict__ rel)
{
    int i = blockIdx.x * blockDim.x + threadIdx.x;
    if (i >= NREL) return;
    atomicAdd(&g_cnt[rel[3 * i + 1]], 1);
    atomicAdd(&g_cnt[NOBJ + rel[3 * i + 2]], 1);
}

__global__ void k_scan()
{
    __shared__ int s[2 * NOBJ];
    int t = threadIdx.x;
    s[t] = g_cnt[t];
    __syncthreads();
    for (int d = 1; d < 2 * NOBJ; d <<= 1) {
        int v = (t >= d) ? s[t - d] : 0;
        __syncthreads();
        s[t] += v;
        __syncthreads();
    }
    g_off[t + 1] = s[t];
    if (t == 0) g_off[0] = 0;
}

// DETERMINISTIC fill: one warp per (role, obj) slot, ballot + prefix-popc.
__global__ void __launch_bounds__(32)
k_fill_det(const int* __restrict__ rel)
{
    const int slot = blockIdx.x;
    const int role = slot >> 9;
    const int obj  = slot & (NOBJ - 1);
    const int lane = threadIdx.x;
    const int fld  = 1 + role;
    int cur = g_off[slot];
    for (int base = 0; base < NREL; base += 32) {
        int i = base + lane;
        int v = rel[3 * i + fld];
        unsigned mask = __ballot_sync(~0u, v == obj);
        if (v == obj) {
            int pos = __popc(mask & ((1u << lane) - 1));
            g_list[cur + pos] = i;
        }
        cur += __popc(mask);
    }
}

// gather-sum (CSR, no atomics), float4
__global__ void k_gather(const float* __restrict__ hr, float* __restrict__ SO)
{
    int obj = blockIdx.x;
    int jj = threadIdx.x * 4;
#pragma unroll
    for (int role = 0; role < 2; role++) {
        int beg = g_off[role * NOBJ + obj];
        int end = g_off[role * NOBJ + obj + 1];
        float4 a = make_float4(0.f, 0.f, 0.f, 0.f);
        for (int p = beg; p < end; p++) {
            const float4 v = *reinterpret_cast<const float4*>(
                &hr[(size_t)g_list[p] * HD + jj]);
            a.x += v.x; a.y += v.y; a.z += v.z; a.w += v.w;
        }
        *reinterpret_cast<float4*>(&SO[(size_t)obj * (2 * HD) + role * HD + jj]) = a;
    }
}

// rel GRU z/r gates: float4, Gso stride 3072
__global__ void k_rel_zr(const float* __restrict__ Azr,
                         const float* __restrict__ Gso,
                         const float* __restrict__ hr,
                         const int* __restrict__ rel,
                         const float* __restrict__ bz,
                         const float* __restrict__ br,
                         float* __restrict__ Z, float* __restrict__ RH)
{
    size_t idx = (size_t)blockIdx.x * blockDim.x + threadIdx.x;
    if (idx >= (size_t)NREL * 128) return;
    int i  = (int)(idx >> 7);
    int jj = (int)(idx & 127) * 4;
    int s = rel[3 * i + 1], o = rel[3 * i + 2];
    const float* gs = Gso + (size_t)s * 3072;
    const float* go = Gso + (size_t)o * 3072 + 1536;
    float4 az = *reinterpret_cast<const float4*>(&Azr[(size_t)i * 1024 + jj]);
    float4 ar = *reinterpret_cast<const float4*>(&Azr[(size_t)i * 1024 + 512 + jj]);
    float4 gsz = *reinterpret_cast<const float4*>(&gs[jj]);
    float4 goz = *reinterpret_cast<const float4*>(&go[jj]);
    float4 gsr = *reinterpret_cast<const float4*>(&gs[512 + jj]);
    float4 gor = *reinterpret_cast<const float4*>(&go[512 + jj]);
    float4 vbz = *reinterpret_cast<const float4*>(&bz[jj]);
    float4 vbr = *reinterpret_cast<const float4*>(&br[jj]);
    float4 h  = *reinterpret_cast<const float4*>(&hr[(size_t)i * HD + jj]);
    float4 z, rh;
    z.x = sigm(az.x + gsz.x + goz.x + vbz.x);
    z.y = sigm(az.y + gsz.y + goz.y + vbz.y);
    z.z = sigm(az.z + gsz.z + goz.z + vbz.z);
    z.w = sigm(az.w + gsz.w + goz.w + vbz.w);
    rh.x = sigm(ar.x + gsr.x + gor.x + vbr.x) * h.x;
    rh.y = sigm(ar.y + gsr.y + gor.y + vbr.y) * h.y;
    rh.z = sigm(ar.z + gsr.z + gor.z + vbr.z) * h.z;
    rh.w = sigm(ar.w + gsr.w + gor.w + vbr.w) * h.w;
    *reinterpret_cast<float4*>(&Z[(size_t)i * HD + jj])  = z;
    *reinterpret_cast<float4*>(&RH[(size_t)i * HD + jj]) = rh;
}

__global__ void k_rel_h(const float* __restrict__ Ah,
                        const float* __restrict__ Gso,
                        const float* __restrict__ Z,
                        const int* __restrict__ rel,
                        const float* __restrict__ bh,
                        float* __restrict__ hr)
{
    size_t idx = (size_t)blockIdx.x * blockDim.x + threadIdx.x;
    if (idx >= (size_t)NREL * 128) return;
    int i  = (int)(idx >> 7);
    int jj = (int)(idx & 127) * 4;
    int s = rel[3 * i + 1], o = rel[3 * i + 2];
    const float4 gsh = *reinterpret_cast<const float4*>(&Gso[(size_t)s * 3072 + 1024 + jj]);
    const float4 goh = *reinterpret_cast<const float4*>(&Gso[(size_t)o * 3072 + 1536 + 1024 + jj]);
    const float4 ah  = *reinterpret_cast<const float4*>(&Ah[(size_t)i * HD + jj]);
    const float4 vbh = *reinterpret_cast<const float4*>(&bh[jj]);
    const float4 z   = *reinterpret_cast<const float4*>(&Z[(size_t)i * HD + jj]);
    float4 h = *reinterpret_cast<float4*>(&hr[(size_t)i * HD + jj]);
    h.x = (1.f - z.x) * h.x + z.x * tanhf(ah.x + gsh.x + goh.x + vbh.x);
    h.y = (1.f - z.y) * h.y + z.y * tanhf(ah.y + gsh.y + goh.y + vbh.y);
    h.z = (1.f - z.z) * h.z + z.z * tanhf(ah.z + gsh.z + goh.z + vbh.z);
    h.w = (1.f - z.w) * h.w + z.w * tanhf(ah.w + gsh.w + goh.w + vbh.w);
    *reinterpret_cast<float4*>(&hr[(size_t)i * HD + jj]) = h;
}

__global__ void k_obj_zr(const float* __restrict__ Azo,
                         const float* __restrict__ bz,
                         const float* __restrict__ br,
                         const float* __restrict__ ho,
                         float* __restrict__ Zo,
                         float* __restrict__ rhO)
{
    size_t idx = (size_t)blockIdx.x * blockDim.x + threadIdx.x;
    if (idx >= (size_t)NOBJ * HD) return;
    int i = (int)(idx >> 9);
    int j = (int)(idx & (HD - 1));
    float az = Azo[(size_t)i * 1024 + j] + bz[j];
    float ar = Azo[(size_t)i * 1024 + 512 + j] + br[j];
    Zo[idx]  = sigm(az);
    rhO[idx] = sigm(ar) * ho[idx];
}

__global__ void k_obj_h(const float* __restrict__ Aho,
                        const float* __restrict__ Zo,
                        const float* __restrict__ bh,
                        float* __restrict__ ho)
{
    size_t idx = (size_t)blockIdx.x * blockDim.x + threadIdx.x;
    if (idx >= (size_t)NOBJ * HD) return;
    int j = (int)(idx & (HD - 1));
    float z = Zo[idx], h = ho[idx];
    ho[idx] = (1.f - z) * h + z * tanhf(Aho[idx] + bh[j]);
}

// ---------------------------------------------------------------------------
// Host-side wrappers
// ---------------------------------------------------------------------------
static inline void mm(int M, int N, int K,
                      const float* A, int lda, const float* BT, int ldb,
                      float* C, int ldc, const float* bias, int acc, int act,
                      float* C2 = nullptr)
{
    dim3 g(N / 128, M / 128);
    mm_f16<2><<<g, 128, MMCfg<2>::SMEM>>>(M, N, K, A, nullptr, 0, lda, BT, ldb,
                                          C, C2, ldc, bias, acc, act);
}

// wide-N variant (BN=256): used whenever M is large and N%256==0
static inline void mm4(int M, int N, int K,
                       const float* A, int lda, const float* BT, int ldb,
                       float* C, int ldc, const float* bias, int acc, int act,
                       float* C2 = nullptr)
{
    dim3 g(N / 256, M / 128);
    mm_f16<4><<<g, 256, MMCfg<4>::SMEM>>>(M, N, K, A, nullptr, 0, lda, BT, ldb,
                                          C, C2, ldc, bias, acc, act);
}

static inline void mm24(int M, int N, int K,
                        const float* A, const float* A2, int kSplit, int lda,
                        const float* BT, int ldb,
                        float* C, int ldc, const float* bias, int acc, int act)
{
    dim3 g(N / 256, M / 128);
    mm_f16<4><<<g, 256, MMCfg<4>::SMEM>>>(M, N, K, A, A2, kSplit, lda, BT, ldb,
                                          C, nullptr, ldc, bias, acc, act);
}

static inline void mm2(int M, int N, int K,
                       const float* A, const float* A2, int kSplit, int lda,
                       const float* BT, int ldb,
                       float* C, int ldc, const float* bias, int acc, int act)
{
    dim3 g(N / 128, M / 128);
    mm_f16<2><<<g, 128, MMCfg<2>::SMEM>>>(M, N, K, A, A2, kSplit, lda, BT, ldb,
                                          C, nullptr, ldc, bias, acc, act);
}

extern "C" void kernel_launch(void* const* d_in, const int* in_sizes, int n_in,
                              void* d_out, int out_size)
{
    (void)in_sizes; (void)n_in; (void)out_size;
    const int*   rel_inds  = (const int*)  d_in[1];
    const float* obj_fmaps = (const float*)d_in[2];
    const float* obj_logit = (const float*)d_in[3];
    const float* vr        = (const float*)d_in[4];
    const float* W_obj = (const float*)d_in[5],  *b_obj = (const float*)d_in[6];
    const float* W_rel = (const float*)d_in[7],  *b_rel = (const float*)d_in[8];
    const float* W_prob= (const float*)d_in[9],  *b_prob= (const float*)d_in[10];
    const float* W_so  = (const float*)d_in[11], *W_oo  = (const float*)d_in[12];
    const float* W_rs  = (const float*)d_in[13], *W_ro  = (const float*)d_in[14];
    const float* Wz = (const float*)d_in[15], *Uz = (const float*)d_in[16], *bz = (const float*)d_in[17];
    const float* Wr = (const float*)d_in[18], *Ur = (const float*)d_in[19], *br = (const float*)d_in[20];
    const float* Wh = (const float*)d_in[21], *Uh = (const float*)d_in[22], *bh = (const float*)d_in[23];
    const float* W_out_rel = (const float*)d_in[24], *b_out_rel = (const float*)d_in[25];
    const float* W_cls_rel = (const float*)d_in[26], *b_cls_rel = (const float*)d_in[27];
    const float* W_out_obj = (const float*)d_in[28], *b_out_obj = (const float*)d_in[29];
    const float* W_cls_obj = (const float*)d_in[30], *b_cls_obj = (const float*)d_in[31];
    float* dout = (float*)d_out;

    cudaFuncSetAttribute(mm_f16<4>, cudaFuncAttributeMaxDynamicSharedMemorySize,
                         MMCfg<4>::SMEM);

    float* sc = nullptr;
    cudaGetSymbolAddress((void**)&sc, g_scratch);
    int* cntp = nullptr;
    cudaGetSymbolAddress((void**)&cntp, g_cnt);

    float* xo     = sc + OFF_XO;
    float* ho     = sc + OFF_HO;
    float* xr     = sc + OFF_XR;
    float* hr     = sc + OFF_HR;
    float* Gso    = sc + OFF_GSO;
    float* SO     = sc + OFF_SO;
    float* mo     = sc + OFF_MO;
    float* rhO    = sc + OFF_RHO;
    float* azrO   = sc + OFF_AZROBJ;
    float* ahO    = sc + OFF_AHOBJ;
    float* zO     = sc + OFF_ZOBJ;
    float* Azr    = sc + OFF_AZR;
    float* Zb     = sc + OFF_Z;
    float* RH     = sc + OFF_RH;
    float* Ahb    = sc + OFF_AH;
    float* Trel   = sc + OFF_TREL;
    float* Tobj   = sc + OFF_TOBJ;
    float* probs  = sc + OFF_PROBS;
    float* PsPoT  = sc + OFF_PSPOT;
    float* WzrhT  = sc + OFF_WZRHT;
    float* UzrT   = sc + OFF_UZRT;
    float* UhT    = sc + OFF_UHT;
    float* WrsroT = sc + OFF_WRSROT;
    float* WzrOT  = sc + OFF_WZROT;
    float* WhOT   = sc + OFF_WHOT;
    float* WrelT  = sc + OFF_WRELT;
    float* WobjT  = sc + OFF_WOBJT;
    float* WorT   = sc + OFF_WORT;
    float* WobT   = sc + OFF_WOBT;
    float* WcrT   = sc + OFF_WCRT;
    float* WcoT   = sc + OFF_WCOT;
    float* RC     = sc + OFF_RC;
    float* OC     = sc + OFF_OC;

    // --- prologue, ordered so launch #6 (ncu -s 5 -c 1) is the big xr GEMM ---
    cudaMemsetAsync(WcrT, 0, (size_t)(128 + 256) * HD * sizeof(float), 0);
    {
        TJobs jobs;
        int n = 0, tiles = 0;
        auto add = [&](const float* src, float* dst, int R, int C, int lds, int ldd) {
            jobs.j[n] = {src, dst, R, C, lds, ldd, tiles};
            tiles += ((C + 31) >> 5) * ((R + 31) >> 5);
            n++;
        };
        add(W_rel, WrelT, DIM, HD, HD, DIM);
        add(W_obj, WobjT, DIM, HD, HD, DIM);
        add(Uz, UzrT,                   HD, HD, HD, HD);
        add(Ur, UzrT + (size_t)HD * HD, HD, HD, HD, HD);
        add(Uh, UhT, HD, HD, HD, HD);
        add(Wz, WzrhT,                       HD, HD, HD, HD);
        add(Wr, WzrhT + (size_t)HD * HD,     HD, HD, HD, HD);
        add(Wh, WzrhT + (size_t)2 * HD * HD, HD, HD, HD, HD);
        add(W_rs, WrsroT,      HD, HD, HD, 2 * HD);
        add(W_ro, WrsroT + HD, HD, HD, HD, 2 * HD);
        add(Wz, WzrOT,                            HD, HD, HD, 2 * HD);
        add(Uz, WzrOT + HD,                       HD, HD, HD, 2 * HD);
        add(Wr, WzrOT + (size_t)HD * 2 * HD,      HD, HD, HD, 2 * HD);
        add(Ur, WzrOT + (size_t)HD * 2 * HD + HD, HD, HD, HD, 2 * HD);
        add(Wh, WhOT,      HD, HD, HD, 2 * HD);
        add(Uh, WhOT + HD, HD, HD, HD, 2 * HD);
        add(W_out_rel, WorT, 2 * HD, HD, HD, 2 * HD);
        add(W_out_obj, WobT, 2 * HD, HD, HD, 2 * HD);
        add(W_cls_rel, WcrT, HD, NRC, NRC, HD);
        add(W_cls_obj, WcoT, HD, NO, NO, HD);
        jobs.njobs = n;
        k_transpose_b<<<tiles, dim3(32, 8)>>>(jobs);
    }
    cudaMemsetAsync(cntp, 0, 2 * NOBJ * sizeof(int), 0);
    k_count<<<(NREL + 255) / 256, 256>>>(rel_inds);
    k_scan<<<1, 2 * NOBJ>>>();

    // xr GEMM (wide-N, launch #6 = profiled); dual-writes xr and hr
    mm4(NREL, HD, DIM, vr, DIM, WrelT, DIM, xr, HD, b_rel, 0, 0, hr);

    k_fill_det<<<2 * NOBJ, 32>>>(rel_inds);

    // PsPoT[3072,512]: rows 0..1535 = WzrhT@W_so^T, rows 1536.. = WzrhT@W_oo^T
    mm(3 * HD, HD, HD, WzrhT, HD, W_so, HD, PsPoT, HD, nullptr, 0, 0);
    mm(3 * HD, HD, HD, WzrhT, HD, W_oo, HD, PsPoT + (size_t)3 * HD * HD, HD,
       nullptr, 0, 0);

    // --- input projections (numeric path identical to rounds 6/9/10) ---
    k_softmax<<<(NOBJ + 7) / 8, dim3(32, 8)>>>(obj_logit, probs, NOBJ, NO);
    mm(NOBJ, HD, DIM, obj_fmaps, DIM, WobjT, DIM, xo, HD, b_obj, 0, 0);
    {
        dim3 g(HD / 64, NOBJ / 64);
        sgemm_gk<<<g, 256>>>(NOBJ, HD, NO, probs, NO, W_prob, HD, xo, ho, HD,
                             b_prob, 1);     // dual-writes ho = xo
    }

    const int relBlocks4 = (int)(((size_t)NREL * 128 + 255) / 256);
    const int objBlocks  = (int)(((size_t)NOBJ * HD + 255) / 256);

    // --- T GGNN steps ---
    for (int t = 0; t < TSTEP; t++) {
        // Gso = ho @ [PsT | PoT]  (512 x 3072); M small -> keep NW=2 grid
        mm(NOBJ, 6 * HD, HD, ho, HD, PsPoT, HD, Gso, 6 * HD, nullptr, 0, 0);

        k_gather<<<NOBJ, 128>>>(hr, SO);

        // obj GRU (small M -> NW=2)
        mm(NOBJ, HD, 2 * HD, SO, 2 * HD, WrsroT, 2 * HD, mo, HD, nullptr, 0, 0);
        mm2(NOBJ, 2 * HD, 2 * HD, mo, ho, HD, HD, WzrOT, 2 * HD, azrO, 2 * HD,
            nullptr, 0, 0);
        k_obj_zr<<<objBlocks, 256>>>(azrO, bz, br, ho, zO, rhO);
        mm2(NOBJ, HD, 2 * HD, mo, rhO, HD, HD, WhOT, 2 * HD, ahO, HD,
            nullptr, 0, 0);

        // rel GRU (big M -> NW=4 wide tiles)
        mm4(NREL, 2 * HD, HD, hr, HD, UzrT, HD, Azr, 2 * HD, nullptr, 0, 0);
        k_rel_zr<<<relBlocks4, 256>>>(Azr, Gso, hr, rel_inds, bz, br, Zb, RH);
        mm4(NREL, HD, HD, RH, HD, UhT, HD, Ahb, HD, nullptr, 0, 0);
        k_rel_h<<<relBlocks4, 256>>>(Ahb, Gso, Zb, rel_inds, bh, hr);

        k_obj_h<<<objBlocks, 256>>>(ahO, zO, bh, ho);
    }

    // --- relation head (big M -> NW=4) ---
    mm24(NREL, HD, 2 * HD, hr, xr, HD, HD, WorT, 2 * HD, Trel, HD,
         b_out_rel, 0, 1);
    mm(NREL, 128, HD, Trel, HD, WcrT, HD, RC, 128, nullptr, 0, 0);
    k_head<<<(NREL + 7) / 8, dim3(32, 8)>>>(RC, 128, b_cls_rel, NRC, NREL,
                                            dout + O_RELL, dout + O_SCP,
                                            nullptr);

    // --- object head (small M -> NW=2) ---
    mm2(NOBJ, HD, 2 * HD, ho, xo, HD, HD, WobT, 2 * HD, Tobj, HD,
        b_out_obj, 0, 1);
    mm(NOBJ, 256, HD, Tobj, HD, WcoT, HD, OC, 256, nullptr, 0, 0);
    k_head<<<(NOBJ + 7) / 8, dim3(32, 8)>>>(OC, 256, b_cls_obj, NO, NOBJ,
                                            dout + O_OBJREF, dout + O_SCENT,
                                            dout + O_PREDS);
}

// round 17
// speedup vs baseline: 1.4174x; 1.4174x over previous
#include <cuda_runtime.h>
#include <math.h>
#include <stdint.h>

// ---------------------------------------------------------------------------
// Problem constants
// ---------------------------------------------------------------------------
namespace {
constexpr int NB = 8, NN = 64, RRI = 2048;
constexpr int DIM = 4096, HD = 512, NO = 151, NRC = 51, TSTEP = 3;
constexpr int NOBJ = NB * NN;    // 512
constexpr int NREL = NB * RRI;   // 16384

// scratch offsets (floats)
constexpr size_t OFF_XO     = 0;
constexpr size_t OFF_HO     = OFF_XO     + (size_t)NOBJ * HD;
constexpr size_t OFF_XR     = OFF_HO     + (size_t)NOBJ * HD;
constexpr size_t OFF_HR     = OFF_XR     + (size_t)NREL * HD;
constexpr size_t OFF_GSO    = OFF_HR     + (size_t)NREL * HD;      // 512x3072
constexpr size_t OFF_SO     = OFF_GSO    + (size_t)NOBJ * 6 * HD;  // 512x1024
constexpr size_t OFF_MO     = OFF_SO     + (size_t)NOBJ * 2 * HD;  // 512x512
constexpr size_t OFF_RHO    = OFF_MO     + (size_t)NOBJ * HD;      // 512x512
constexpr size_t OFF_AZROBJ = OFF_RHO    + (size_t)NOBJ * HD;      // 512x1024
constexpr size_t OFF_AHOBJ  = OFF_AZROBJ + (size_t)NOBJ * 2 * HD;  // 512x512
constexpr size_t OFF_ZOBJ   = OFF_AHOBJ  + (size_t)NOBJ * HD;      // 512x512
constexpr size_t OFF_AZR    = OFF_ZOBJ   + (size_t)NOBJ * HD;      // 16384x1024
constexpr size_t OFF_Z      = OFF_AZR    + (size_t)NREL * 2 * HD;
constexpr size_t OFF_RH     = OFF_Z      + (size_t)NREL * HD;
constexpr size_t OFF_AH     = OFF_RH     + (size_t)NREL * HD;
constexpr size_t OFF_TREL   = OFF_AH     + (size_t)NREL * HD;
constexpr size_t OFF_TOBJ   = OFF_TREL   + (size_t)NREL * HD;
constexpr size_t OFF_PROBS  = OFF_TOBJ   + (size_t)NOBJ * HD;      // 512x151
// transposed / padded weights ([N,K] row-major for the GEMM's B operand)
constexpr size_t OFF_PSPOT  = OFF_PROBS  + (size_t)NOBJ * NO;      // 3072x512
constexpr size_t OFF_WZRHT  = OFF_PSPOT  + (size_t)6 * HD * HD;    // 1536x512
constexpr size_t OFF_UZRT   = OFF_WZRHT  + (size_t)3 * HD * HD;    // 1024x512
constexpr size_t OFF_UHT    = OFF_UZRT   + (size_t)2 * HD * HD;    // 512x512
constexpr size_t OFF_WRSROT = OFF_UHT    + (size_t)HD * HD;        // 512x1024
constexpr size_t OFF_WZROT  = OFF_WRSROT + (size_t)HD * 2 * HD;    // 1024x1024
constexpr size_t OFF_WHOT   = OFF_WZROT  + (size_t)2 * HD * 2 * HD;// 512x1024
constexpr size_t OFF_WRELT  = OFF_WHOT   + (size_t)HD * 2 * HD;    // 512x4096
constexpr size_t OFF_WOBJT  = OFF_WRELT  + (size_t)HD * DIM;       // 512x4096
constexpr size_t OFF_WORT   = OFF_WOBJT  + (size_t)HD * DIM;       // 512x1024
constexpr size_t OFF_WOBT   = OFF_WORT   + (size_t)HD * 2 * HD;    // 512x1024
constexpr size_t OFF_WCRT   = OFF_WOBT   + (size_t)HD * 2 * HD;    // 128x512
constexpr size_t OFF_WCOT   = OFF_WCRT   + (size_t)128 * HD;       // 256x512
constexpr size_t OFF_RC     = OFF_WCOT   + (size_t)256 * HD;       // 16384x128
constexpr size_t OFF_OC     = OFF_RC     + (size_t)NREL * 128;     // 512x256
constexpr size_t SCRATCH_FLOATS = OFF_OC + (size_t)NOBJ * 256 + 1024;

// output offsets (floats), tuple order of the reference return
constexpr size_t O_OBJREF = 0;                                  // 512*151
constexpr size_t O_PREDS  = O_OBJREF + (size_t)NOBJ * NO;       // 512
constexpr size_t O_RELL   = O_PREDS  + (size_t)NOBJ;            // 16384*51
constexpr size_t O_SCP    = O_RELL   + (size_t)NREL * NRC;      // 16384*51
constexpr size_t O_SCENT  = O_SCP    + (size_t)NREL * NRC;      // 512*151
}

__device__ float g_scratch[SCRATCH_FLOATS];

// CSR for scatter->gather conversion (built once per launch, DETERMINISTIC)
__device__ int g_cnt[2 * NOBJ];
__device__ int g_off[2 * NOBJ + 1];
__device__ int g_list[2 * NREL];

__device__ __forceinline__ float sigm(float x) { return 1.f / (1.f + expf(-x)); }

// ---------------------------------------------------------------------------
// FP16 tensor-core GEMM (mma.sync.m16n8k16, fp32 accum), fragment-major SMEM,
// double-buffered (single sync/chunk). Templated on NW = warps along N.
// BN = 64*NW, threads = 64*NW (warp grid 2 x NW), warp tile ALWAYS 64x64.
// FLOAT4 prefetch staging (round-10 champion config; half2 staging measured
// as a regression in round 16 and is NOT used).
// Per-output-element K accumulation order IDENTICAL for all NW (numerics
// frozen; NW tiling proven bit-neutral in rounds 10/11/15/16).
// C[M,N] (= or +=) [A | A2][M,K] @ BT[N,K]^T (+bias)(tanh), optional dual out.
// ---------------------------------------------------------------------------
__device__ __forceinline__ unsigned pack_h2(float x, float y) {
    unsigned u;
    asm("{ .reg .f16 lo, hi;\n\t"
        "cvt.rn.f16.f32 lo, %1; cvt.rn.f16.f32 hi, %2;\n\t"
        "mov.b32 %0, {lo, hi}; }"
        : "=r"(u) : "f"(x), "f"(y));
    return u;
}

constexpr int A_FRAG_STRIDE = 132;
constexpr int B_FRAG_STRIDE = 66;
constexpr int A_REGION_U32  = 16 * A_FRAG_STRIDE;   // 2112 (BM=128 always)

template<int NW>
struct MMCfg {
    static constexpr int THREADS = 64 * NW;
    static constexpr int BN      = 64 * NW;
    static constexpr int B_REGION_U32 = 16 * NW * B_FRAG_STRIDE;
    static constexpr int BUF_U32 = A_REGION_U32 + B_REGION_U32;
    static constexpr int SMEM    = 2 * BUF_U32 * 4;
    static constexpr int IA      = 16 / NW;   // A float4 loads per thread
};

template<int NW>
__global__ void __launch_bounds__(64 * NW)
mm_f16(int M, int N, int K,
       const float* __restrict__ A, const float* __restrict__ A2,
       int kSplit, int lda,
       const float* __restrict__ BT, int ldb,
       float* __restrict__ C, float* __restrict__ C2, int ldc,
       const float* __restrict__ bias, int accFlag, int act)
{
    using Cfg = MMCfg<NW>;
    extern __shared__ unsigned smv[];
    const int tid  = threadIdx.x;
    const int lane = tid & 31;
    const int warp = tid >> 5;
    const int wm   = warp / NW;     // 0..1
    const int wn   = warp % NW;     // 0..NW-1
    const int m0   = blockIdx.y * 128;
    const int n0   = blockIdx.x * Cfg::BN;

    float acc[4][8][4];
#pragma unroll
    for (int mf = 0; mf < 4; mf++)
#pragma unroll
        for (int nf = 0; nf < 8; nf++)
#pragma unroll
            for (int i = 0; i < 4; i++) acc[mf][nf][i] = 0.f;

    float4 ra[Cfg::IA], rb[8];

    auto ldgA = [&](int c) {
        int k0 = c * 32;
        const float* Ap = A;
        if (kSplit && k0 >= kSplit) { Ap = A2; k0 -= kSplit; }
#pragma unroll
        for (int i = 0; i < Cfg::IA; i++) {
            int idx = tid + i * Cfg::THREADS;
            int row = idx >> 3, cc = (idx & 7) << 2;
            ra[i] = *reinterpret_cast<const float4*>(
                &Ap[(size_t)(m0 + row) * lda + k0 + cc]);
        }
    };
    auto ldgB = [&](int c) {
        int k0 = c * 32;
#pragma unroll
        for (int i = 0; i < 8; i++) {
            int idx = tid + i * Cfg::THREADS;
            int row = idx >> 3, cc = (idx & 7) << 2;
            rb[i] = *reinterpret_cast<const float4*>(
                &BT[(size_t)(n0 + row) * ldb + k0 + cc]);
        }
    };
    auto sts = [&](int b) {
        unsigned* Ab = &smv[b * Cfg::BUF_U32];
        unsigned* Bb = Ab + A_REGION_U32;
#pragma unroll
        for (int i = 0; i < Cfg::IA; i++) {
            int idx = tid + i * Cfg::THREADS;
            int row = idx >> 3, c0 = (idx & 7) << 2;
            int kb  = (c0 >> 4) & 1;
            int f   = ((row >> 4) << 1) | kb;
            int r   = ((row >> 3) & 1) | (((c0 >> 3) & 1) << 1);
            int tg0 = (c0 & 7) >> 1;                    // 0 or 2
            int lane0 = ((row & 7) << 2) | tg0;
            int base = f * A_FRAG_STRIDE + lane0 * 4 + r;
            Ab[base]     = pack_h2(ra[i].x, ra[i].y);
            Ab[base + 4] = pack_h2(ra[i].z, ra[i].w);
        }
#pragma unroll
        for (int i = 0; i < 8; i++) {
            int idx = tid + i * Cfg::THREADS;
            int n = idx >> 3, c0 = (idx & 7) << 2;
            int kb  = (c0 >> 4) & 1;
            int f   = ((n >> 3) << 1) | kb;
            int r   = (c0 >> 3) & 1;
            int tg0 = (c0 & 7) >> 1;
            int lane0 = ((n & 7) << 2) | tg0;
            int base = f * B_FRAG_STRIDE + lane0 * 2 + r;
            Bb[base]     = pack_h2(rb[i].x, rb[i].y);
            Bb[base + 2] = pack_h2(rb[i].z, rb[i].w);
        }
    };
    auto compute = [&](int b, int kbFrom, int kbTo) {
        const unsigned* Ab = &smv[b * Cfg::BUF_U32];
        const unsigned* Bb = Ab + A_REGION_U32;
#pragma unroll
        for (int kb = kbFrom; kb < kbTo; kb++) {
            uint4 a[4];
            uint2 bf[8];
#pragma unroll
            for (int mf = 0; mf < 4; mf++) {
                int f = ((wm * 4 + mf) << 1) | kb;
                a[mf] = *reinterpret_cast<const uint4*>(
                    &Ab[f * A_FRAG_STRIDE + lane * 4]);
            }
#pragma unroll
            for (int nf = 0; nf < 8; nf++) {
                int f = ((wn * 8 + nf) << 1) | kb;
                bf[nf] = *reinterpret_cast<const uint2*>(
                    &Bb[f * B_FRAG_STRIDE + lane * 2]);
            }
#pragma unroll
            for (int mf = 0; mf < 4; mf++)
#pragma unroll
                for (int nf = 0; nf < 8; nf++) {
                    asm volatile(
                        "mma.sync.aligned.m16n8k16.row.col.f32.f16.f16.f32 "
                        "{%0,%1,%2,%3},{%4,%5,%6,%7},{%8,%9},{%0,%1,%2,%3};"
                        : "+f"(acc[mf][nf][0]), "+f"(acc[mf][nf][1]),
                          "+f"(acc[mf][nf][2]), "+f"(acc[mf][nf][3])
                        : "r"(a[mf].x), "r"(a[mf].y), "r"(a[mf].z), "r"(a[mf].w),
                          "r"(bf[nf].x), "r"(bf[nf].y));
                }
        }
    };

    const int nc = K / 32;
    ldgA(0); ldgB(0);
    sts(0);
    __syncthreads();

    for (int c = 0; c < nc; c++) {
        const int b = c & 1;
        if (c + 1 < nc) ldgA(c + 1);
        compute(b, 0, 1);
        if (c + 1 < nc) ldgB(c + 1);
        compute(b, 1, 2);
        if (c + 1 < nc) {
            sts(1 - b);          // other buffer; its readers synced at c-1
            __syncthreads();     // single barrier per chunk
        }
    }

    // epilogue
    const int g  = lane >> 2;
    const int tg = lane & 3;
#pragma unroll
    for (int mf = 0; mf < 4; mf++) {
        const int r0 = m0 + wm * 64 + mf * 16 + g;
#pragma unroll
        for (int nf = 0; nf < 8; nf++) {
            const int c0 = n0 + wn * 64 + nf * 8 + tg * 2;
#pragma unroll
            for (int h = 0; h < 2; h++) {
                const int row = r0 + h * 8;
                float vx = acc[mf][nf][2 * h + 0];
                float vy = acc[mf][nf][2 * h + 1];
                size_t off = (size_t)row * ldc + c0;
                if (accFlag) {
                    float2 o = *reinterpret_cast<const float2*>(&C[off]);
                    vx += o.x; vy += o.y;
                }
                if (bias) { vx += bias[c0]; vy += bias[c0 + 1]; }
                if (act == 1) { vx = tanhf(vx); vy = tanhf(vy); }
                float2 o2; o2.x = vx; o2.y = vy;
                *reinterpret_cast<float2*>(&C[off]) = o2;
                if (C2) *reinterpret_cast<float2*>(&C2[off]) = o2;
            }
        }
    }
}

// ---------------------------------------------------------------------------
// FP32 tiled SGEMM (only for ragged-K probs @ W_prob), optional dual-write
// ---------------------------------------------------------------------------
__global__ void sgemm_gk(int M, int N, int K,
                         const float* __restrict__ A, int lda,
                         const float* __restrict__ B, int ldb,
                         float* __restrict__ C, float* __restrict__ C2, int ldc,
                         const float* __restrict__ bias, int accFlag)
{
    constexpr int BM = 64, BN = 64, BK = 16, TM = 4, TN = 4;
    constexpr int TX = BN / TN;
    __shared__ float As[BK][BM];
    __shared__ float Bs[BK][BN];
    const int tid = threadIdx.x;
    const int tr = tid / TX, tc = tid % TX;
    const int rowBase = blockIdx.y * BM, colBase = blockIdx.x * BN;
    float acc[TM][TN];
#pragma unroll
    for (int i = 0; i < TM; i++)
#pragma unroll
        for (int j = 0; j < TN; j++) acc[i][j] = 0.f;
    const int arow = tid / (BK / 4), acol = (tid % (BK / 4)) * 4;
    const int brow = tid / (BN / 4), bcol = (tid % (BN / 4)) * 4;
    for (int k0 = 0; k0 < K; k0 += BK) {
#pragma unroll
        for (int j = 0; j < 4; j++) {
            int gk = k0 + acol + j;
            As[acol + j][arow] = (gk < K) ? A[(size_t)(rowBase + arow) * lda + gk] : 0.f;
        }
#pragma unroll
        for (int j = 0; j < 4; j++) {
            int gk = k0 + brow;
            Bs[brow][bcol + j] = (gk < K) ? B[(size_t)gk * ldb + colBase + bcol + j] : 0.f;
        }
        __syncthreads();
#pragma unroll
        for (int kk = 0; kk < BK; kk++) {
            float ra[TM], rb[TN];
#pragma unroll
            for (int i = 0; i < TM; i++) ra[i] = As[kk][tr * TM + i];
#pragma unroll
            for (int j = 0; j < TN; j++) rb[j] = Bs[kk][tc * TN + j];
#pragma unroll
            for (int i = 0; i < TM; i++)
#pragma unroll
                for (int j = 0; j < TN; j++) acc[i][j] += ra[i] * rb[j];
        }
        __syncthreads();
    }
#pragma unroll
    for (int i = 0; i < TM; i++) {
        int gr = rowBase + tr * TM + i;
#pragma unroll
        for (int j = 0; j < TN; j++) {
            int gc = colBase + tc * TN + j;
            float v = acc[i][j];
            size_t off = (size_t)gr * ldc + gc;
            if (accFlag) v += C[off];
            if (bias) v += bias[gc];
            C[off] = v;
            if (C2) C2[off] = v;
        }
    }
}

// ---------------------------------------------------------------------------
// Batched transpose: all weight transposes in ONE launch.
// ---------------------------------------------------------------------------
struct TJob { const float* src; float* dst; int R, C, lds, ldd, tileStart; };
struct TJobs { TJob j[20]; int njobs; };

__global__ void k_transpose_b(TJobs jobs)
{
    __shared__ float t[32][33];
    const int bid = blockIdx.x;
    int lo = 0;
#pragma unroll 1
    for (int k = 1; k < jobs.njobs; k++)
        if (jobs.j[k].tileStart <= bid) lo = k;
    const TJob jb = jobs.j[lo];
    const int lt = bid - jb.tileStart;
    const int tx_n = (jb.C + 31) >> 5;
    const int cb = (lt % tx_n) * 32;
    const int rb = (lt / tx_n) * 32;
    const int tx = threadIdx.x, ty = threadIdx.y;
#pragma unroll
    for (int i = 0; i < 4; i++) {
        int r = rb + ty + i * 8, c = cb + tx;
        if (r < jb.R && c < jb.C) t[ty + i * 8][tx] = jb.src[(size_t)r * jb.lds + c];
    }
    __syncthreads();
#pragma unroll
    for (int i = 0; i < 4; i++) {
        int c = cb + ty + i * 8, r = rb + tx;
        if (c < jb.C && r < jb.R) jb.dst[(size_t)c * jb.ldd + r] = t[tx][ty + i * 8];
    }
}

// ---------------------------------------------------------------------------
// Elementwise / utility kernels
// ---------------------------------------------------------------------------
__global__ void k_softmax(const float* __restrict__ in, float* __restrict__ out,
                          int rows, int cols)
{
    int row = blockIdx.x * blockDim.y + threadIdx.y;
    if (row >= rows) return;
    int lane = threadIdx.x;
    const float* r = in + (size_t)row * cols;
    float m = __int_as_float(0xff800000);
    for (int c = lane; c < cols; c += 32) m = fmaxf(m, r[c]);
    for (int o = 16; o; o >>= 1) m = fmaxf(m, __shfl_xor_sync(~0u, m, o));
    float s = 0.f;
    for (int c = lane; c < cols; c += 32) s += expf(r[c] - m);
    for (int o = 16; o; o >>= 1) s += __shfl_xor_sync(~0u, s, o);
    float inv = 1.f / s;
    float* w = out + (size_t)row * cols;
    for (int c = lane; c < cols; c += 32) w[c] = expf(r[c] - m) * inv;
}

// fused head: logits = in[:, :cols] + bias ; softmax ; optional argmax[1:]
__global__ void k_head(const float* __restrict__ in, int ldin,
                       const float* __restrict__ bias, int cols, int rows,
                       float* __restrict__ logits, float* __restrict__ sm,
                       float* __restrict__ preds)
{
    int row = blockIdx.x * blockDim.y + threadIdx.y;
    if (row >= rows) return;
    int lane = threadIdx.x;
    const float* r = in + (size_t)row * ldin;
    float m = __int_as_float(0xff800000);
    float bv = __int_as_float(0xff800000);
    int bi = cols;
    for (int c = lane; c < cols; c += 32) {
        float t = r[c] + bias[c];
        m = fmaxf(m, t);
        if (c >= 1 && (t > bv || (t == bv && c < bi))) { bv = t; bi = c; }
    }
    for (int o = 16; o; o >>= 1) m = fmaxf(m, __shfl_xor_sync(~0u, m, o));
    if (preds) {
        for (int o = 16; o; o >>= 1) {
            float ov = __shfl_xor_sync(~0u, bv, o);
            int oi = __shfl_xor_sync(~0u, bi, o);
            if (ov > bv || (ov == bv && oi < bi)) { bv = ov; bi = oi; }
        }
        if (lane == 0) preds[row] = (float)bi;
    }
    float s = 0.f;
    for (int c = lane; c < cols; c += 32) s += expf(r[c] + bias[c] - m);
    for (int o = 16; o; o >>= 1) s += __shfl_xor_sync(~0u, s, o);
    float inv = 1.f / s;
    for (int c = lane; c < cols; c += 32) {
        float t = r[c] + bias[c];
        logits[(size_t)row * cols + c] = t;
        sm[(size_t)row * cols + c] = expf(t - m) * inv;
    }
}

// --- CSR build (once per launch) ---
__global__ void k_count(const int* __restrict__ rel)
{
    int i = blockIdx.x * blockDim.x + threadIdx.x;
    if (i >= NREL) return;
    atomicAdd(&g_cnt[rel[3 * i + 1]], 1);
    atomicAdd(&g_cnt[NOBJ + rel[3 * i + 2]], 1);
}

__global__ void k_scan()
{
    __shared__ int s[2 * NOBJ];
    int t = threadIdx.x;
    s[t] = g_cnt[t];
    __syncthreads();
    for (int d = 1; d < 2 * NOBJ; d <<= 1) {
        int v = (t >= d) ? s[t - d] : 0;
        __syncthreads();
        s[t] += v;
        __syncthreads();
    }
    g_off[t + 1] = s[t];
    if (t == 0) g_off[0] = 0;
}

// DETERMINISTIC fill: one warp per (role, obj) slot, ballot + prefix-popc.
__global__ void __launch_bounds__(32)
k_fill_det(const int* __restrict__ rel)
{
    const int slot = blockIdx.x;
    const int role = slot >> 9;
    const int obj  = slot & (NOBJ - 1);
    const int lane = threadIdx.x;
    const int fld  = 1 + role;
    int cur = g_off[slot];
    for (int base = 0; base < NREL; base += 32) {
        int i = base + lane;
        int v = rel[3 * i + fld];
        unsigned mask = __ballot_sync(~0u, v == obj);
        if (v == obj) {
            int pos = __popc(mask & ((1u << lane) - 1));
            g_list[cur + pos] = i;
        }
        cur += __popc(mask);
    }
}

// gather-sum (CSR, no atomics), float4
__global__ void k_gather(const float* __restrict__ hr, float* __restrict__ SO)
{
    int obj = blockIdx.x;
    int jj = threadIdx.x * 4;
#pragma unroll
    for (int role = 0; role < 2; role++) {
        int beg = g_off[role * NOBJ + obj];
        int end = g_off[role * NOBJ + obj + 1];
        float4 a = make_float4(0.f, 0.f, 0.f, 0.f);
        for (int p = beg; p < end; p++) {
            const float4 v = *reinterpret_cast<const float4*>(
                &hr[(size_t)g_list[p] * HD + jj]);
            a.x += v.x; a.y += v.y; a.z += v.z; a.w += v.w;
        }
        *reinterpret_cast<float4*>(&SO[(size_t)obj * (2 * HD) + role * HD + jj]) = a;
    }
}

// rel GRU z/r gates: float4, Gso stride 3072
__global__ void k_rel_zr(const float* __restrict__ Azr,
                         const float* __restrict__ Gso,
                         const float* __restrict__ hr,
                         const int* __restrict__ rel,
                         const float* __restrict__ bz,
                         const float* __restrict__ br,
                         float* __restrict__ Z, float* __restrict__ RH)
{
    size_t idx = (size_t)blockIdx.x * blockDim.x + threadIdx.x;
    if (idx >= (size_t)NREL * 128) return;
    int i  = (int)(idx >> 7);
    int jj = (int)(idx & 127) * 4;
    int s = rel[3 * i + 1], o = rel[3 * i + 2];
    const float* gs = Gso + (size_t)s * 3072;
    const float* go = Gso + (size_t)o * 3072 + 1536;
    float4 az = *reinterpret_cast<const float4*>(&Azr[(size_t)i * 1024 + jj]);
    float4 ar = *reinterpret_cast<const float4*>(&Azr[(size_t)i * 1024 + 512 + jj]);
    float4 gsz = *reinterpret_cast<const float4*>(&gs[jj]);
    float4 goz = *reinterpret_cast<const float4*>(&go[jj]);
    float4 gsr = *reinterpret_cast<const float4*>(&gs[512 + jj]);
    float4 gor = *reinterpret_cast<const float4*>(&go[512 + jj]);
    float4 vbz = *reinterpret_cast<const float4*>(&bz[jj]);
    float4 vbr = *reinterpret_cast<const float4*>(&br[jj]);
    float4 h  = *reinterpret_cast<const float4*>(&hr[(size_t)i * HD + jj]);
    float4 z, rh;
    z.x = sigm(az.x + gsz.x + goz.x + vbz.x);
    z.y = sigm(az.y + gsz.y + goz.y + vbz.y);
    z.z = sigm(az.z + gsz.z + goz.z + vbz.z);
    z.w = sigm(az.w + gsz.w + goz.w + vbz.w);
    rh.x = sigm(ar.x + gsr.x + gor.x + vbr.x) * h.x;
    rh.y = sigm(ar.y + gsr.y + gor.y + vbr.y) * h.y;
    rh.z = sigm(ar.z + gsr.z + gor.z + vbr.z) * h.z;
    rh.w = sigm(ar.w + gsr.w + gor.w + vbr.w) * h.w;
    *reinterpret_cast<float4*>(&Z[(size_t)i * HD + jj])  = z;
    *reinterpret_cast<float4*>(&RH[(size_t)i * HD + jj]) = rh;
}

__global__ void k_rel_h(const float* __restrict__ Ah,
                        const float* __restrict__ Gso,
                        const float* __restrict__ Z,
                        const int* __restrict__ rel,
                        const float* __restrict__ bh,
                        float* __restrict__ hr)
{
    size_t idx = (size_t)blockIdx.x * blockDim.x + threadIdx.x;
    if (idx >= (size_t)NREL * 128) return;
    int i  = (int)(idx >> 7);
    int jj = (int)(idx & 127) * 4;
    int s = rel[3 * i + 1], o = rel[3 * i + 2];
    const float4 gsh = *reinterpret_cast<const float4*>(&Gso[(size_t)s * 3072 + 1024 + jj]);
    const float4 goh = *reinterpret_cast<const float4*>(&Gso[(size_t)o * 3072 + 1536 + 1024 + jj]);
    const float4 ah  = *reinterpret_cast<const float4*>(&Ah[(size_t)i * HD + jj]);
    const float4 vbh = *reinterpret_cast<const float4*>(&bh[jj]);
    const float4 z   = *reinterpret_cast<const float4*>(&Z[(size_t)i * HD + jj]);
    float4 h = *reinterpret_cast<float4*>(&hr[(size_t)i * HD + jj]);
    h.x = (1.f - z.x) * h.x + z.x * tanhf(ah.x + gsh.x + goh.x + vbh.x);
    h.y = (1.f - z.y) * h.y + z.y * tanhf(ah.y + gsh.y + goh.y + vbh.y);
    h.z = (1.f - z.z) * h.z + z.z * tanhf(ah.z + gsh.z + goh.z + vbh.z);
    h.w = (1.f - z.w) * h.w + z.w * tanhf(ah.w + gsh.w + goh.w + vbh.w);
    *reinterpret_cast<float4*>(&hr[(size_t)i * HD + jj]) = h;
}

__global__ void k_obj_zr(const float* __restrict__ Azo,
                         const float* __restrict__ bz,
                         const float* __restrict__ br,
                         const float* __restrict__ ho,
                         float* __restrict__ Zo,
                         float* __restrict__ rhO)
{
    size_t idx = (size_t)blockIdx.x * blockDim.x + threadIdx.x;
    if (idx >= (size_t)NOBJ * HD) return;
    int i = (int)(idx >> 9);
    int j = (int)(idx & (HD - 1));
    float az = Azo[(size_t)i * 1024 + j] + bz[j];
    float ar = Azo[(size_t)i * 1024 + 512 + j] + br[j];
    Zo[idx]  = sigm(az);
    rhO[idx] = sigm(ar) * ho[idx];
}

__global__ void k_obj_h(const float* __restrict__ Aho,
                        const float* __restrict__ Zo,
                        const float* __restrict__ bh,
                        float* __restrict__ ho)
{
    size_t idx = (size_t)blockIdx.x * blockDim.x + threadIdx.x;
    if (idx >= (size_t)NOBJ * HD) return;
    int j = (int)(idx & (HD - 1));
    float z = Zo[idx], h = ho[idx];
    ho[idx] = (1.f - z) * h + z * tanhf(Aho[idx] + bh[j]);
}

// ---------------------------------------------------------------------------
// Host-side wrappers
// ---------------------------------------------------------------------------
static inline void mm(int M, int N, int K,
                      const float* A, int lda, const float* BT, int ldb,
                      float* C, int ldc, const float* bias, int acc, int act,
                      float* C2 = nullptr)
{
    dim3 g(N / 128, M / 128);
    mm_f16<2><<<g, 128, MMCfg<2>::SMEM>>>(M, N, K, A, nullptr, 0, lda, BT, ldb,
                                          C, C2, ldc, bias, acc, act);
}

// wide-N variant (BN=256) for large-M GEMMs with N%256==0
static inline void mm4(int M, int N, int K,
                       const float* A, int lda, const float* BT, int ldb,
                       float* C, int ldc, const float* bias, int acc, int act,
                       float* C2 = nullptr)
{
    dim3 g(N / 256, M / 128);
    mm_f16<4><<<g, 256, MMCfg<4>::SMEM>>>(M, N, K, A, nullptr, 0, lda, BT, ldb,
                                          C, C2, ldc, bias, acc, act);
}

static inline void mm24(int M, int N, int K,
                        const float* A, const float* A2, int kSplit, int lda,
                        const float* BT, int ldb,
                        float* C, int ldc, const float* bias, int acc, int act)
{
    dim3 g(N / 256, M / 128);
    mm_f16<4><<<g, 256, MMCfg<4>::SMEM>>>(M, N, K, A, A2, kSplit, lda, BT, ldb,
                                          C, nullptr, ldc, bias, acc, act);
}

static inline void mm2(int M, int N, int K,
                       const float* A, const float* A2, int kSplit, int lda,
                       const float* BT, int ldb,
                       float* C, int ldc, const float* bias, int acc, int act)
{
    dim3 g(N / 128, M / 128);
    mm_f16<2><<<g, 128, MMCfg<2>::SMEM>>>(M, N, K, A, A2, kSplit, lda, BT, ldb,
                                          C, nullptr, ldc, bias, acc, act);
}

extern "C" void kernel_launch(void* const* d_in, const int* in_sizes, int n_in,
                              void* d_out, int out_size)
{
    (void)in_sizes; (void)n_in; (void)out_size;
    const int*   rel_inds  = (const int*)  d_in[1];
    const float* obj_fmaps = (const float*)d_in[2];
    const float* obj_logit = (const float*)d_in[3];
    const float* vr        = (const float*)d_in[4];
    const float* W_obj = (const float*)d_in[5],  *b_obj = (const float*)d_in[6];
    const float* W_rel = (const float*)d_in[7],  *b_rel = (const float*)d_in[8];
    const float* W_prob= (const float*)d_in[9],  *b_prob= (const float*)d_in[10];
    const float* W_so  = (const float*)d_in[11], *W_oo  = (const float*)d_in[12];
    const float* W_rs  = (const float*)d_in[13], *W_ro  = (const float*)d_in[14];
    const float* Wz = (const float*)d_in[15], *Uz = (const float*)d_in[16], *bz = (const float*)d_in[17];
    const float* Wr = (const float*)d_in[18], *Ur = (const float*)d_in[19], *br = (const float*)d_in[20];
    const float* Wh = (const float*)d_in[21], *Uh = (const float*)d_in[22], *bh = (const float*)d_in[23];
    const float* W_out_rel = (const float*)d_in[24], *b_out_rel = (const float*)d_in[25];
    const float* W_cls_rel = (const float*)d_in[26], *b_cls_rel = (const float*)d_in[27];
    const float* W_out_obj = (const float*)d_in[28], *b_out_obj = (const float*)d_in[29];
    const float* W_cls_obj = (const float*)d_in[30], *b_cls_obj = (const float*)d_in[31];
    float* dout = (float*)d_out;

    cudaFuncSetAttribute(mm_f16<4>, cudaFuncAttributeMaxDynamicSharedMemorySize,
                         MMCfg<4>::SMEM);

    float* sc = nullptr;
    cudaGetSymbolAddress((void**)&sc, g_scratch);
    int* cntp = nullptr;
    cudaGetSymbolAddress((void**)&cntp, g_cnt);

    float* xo     = sc + OFF_XO;
    float* ho     = sc + OFF_HO;
    float* xr     = sc + OFF_XR;
    float* hr     = sc + OFF_HR;
    float* Gso    = sc + OFF_GSO;
    float* SO     = sc + OFF_SO;
    float* mo     = sc + OFF_MO;
    float* rhO    = sc + OFF_RHO;
    float* azrO   = sc + OFF_AZROBJ;
    float* ahO    = sc + OFF_AHOBJ;
    float* zO     = sc + OFF_ZOBJ;
    float* Azr    = sc + OFF_AZR;
    float* Zb     = sc + OFF_Z;
    float* RH     = sc + OFF_RH;
    float* Ahb    = sc + OFF_AH;
    float* Trel   = sc + OFF_TREL;
    float* Tobj   = sc + OFF_TOBJ;
    float* probs  = sc + OFF_PROBS;
    float* PsPoT  = sc + OFF_PSPOT;
    float* WzrhT  = sc + OFF_WZRHT;
    float* UzrT   = sc + OFF_UZRT;
    float* UhT    = sc + OFF_UHT;
    float* WrsroT = sc + OFF_WRSROT;
    float* WzrOT  = sc + OFF_WZROT;
    float* WhOT   = sc + OFF_WHOT;
    float* WrelT  = sc + OFF_WRELT;
    float* WobjT  = sc + OFF_WOBJT;
    float* WorT   = sc + OFF_WORT;
    float* WobT   = sc + OFF_WOBT;
    float* WcrT   = sc + OFF_WCRT;
    float* WcoT   = sc + OFF_WCOT;
    float* RC     = sc + OFF_RC;
    float* OC     = sc + OFF_OC;

    // --- prologue, ordered so launch #6 (ncu -s 5 -c 1) is the big xr GEMM ---
    cudaMemsetAsync(WcrT, 0, (size_t)(128 + 256) * HD * sizeof(float), 0);
    {
        TJobs jobs;
        int n = 0, tiles = 0;
        auto add = [&](const float* src, float* dst, int R, int C, int lds, int ldd) {
            jobs.j[n] = {src, dst, R, C, lds, ldd, tiles};
            tiles += ((C + 31) >> 5) * ((R + 31) >> 5);
            n++;
        };
        add(W_rel, WrelT, DIM, HD, HD, DIM);
        add(W_obj, WobjT, DIM, HD, HD, DIM);
        add(Uz, UzrT,                   HD, HD, HD, HD);
        add(Ur, UzrT + (size_t)HD * HD, HD, HD, HD, HD);
        add(Uh, UhT, HD, HD, HD, HD);
        add(Wz, WzrhT,                       HD, HD, HD, HD);
        add(Wr, WzrhT + (size_t)HD * HD,     HD, HD, HD, HD);
        add(Wh, WzrhT + (size_t)2 * HD * HD, HD, HD, HD, HD);
        add(W_rs, WrsroT,      HD, HD, HD, 2 * HD);
        add(W_ro, WrsroT + HD, HD, HD, HD, 2 * HD);
        add(Wz, WzrOT,                            HD, HD, HD, 2 * HD);
        add(Uz, WzrOT + HD,                       HD, HD, HD, 2 * HD);
        add(Wr, WzrOT + (size_t)HD * 2 * HD,      HD, HD, HD, 2 * HD);
        add(Ur, WzrOT + (size_t)HD * 2 * HD + HD, HD, HD, HD, 2 * HD);
        add(Wh, WhOT,      HD, HD, HD, 2 * HD);
        add(Uh, WhOT + HD, HD, HD, HD, 2 * HD);
        add(W_out_rel, WorT, 2 * HD, HD, HD, 2 * HD);
        add(W_out_obj, WobT, 2 * HD, HD, HD, 2 * HD);
        add(W_cls_rel, WcrT, HD, NRC, NRC, HD);
        add(W_cls_obj, WcoT, HD, NO, NO, HD);
        jobs.njobs = n;
        k_transpose_b<<<tiles, dim3(32, 8)>>>(jobs);
    }
    cudaMemsetAsync(cntp, 0, 2 * NOBJ * sizeof(int), 0);
    k_count<<<(NREL + 255) / 256, 256>>>(rel_inds);
    k_scan<<<1, 2 * NOBJ>>>();

    // xr GEMM (wide-N, launch #6 = profiled); dual-writes xr and hr
    mm4(NREL, HD, DIM, vr, DIM, WrelT, DIM, xr, HD, b_rel, 0, 0, hr);

    k_fill_det<<<2 * NOBJ, 32>>>(rel_inds);

    // PsPoT[3072,512]: rows 0..1535 = WzrhT@W_so^T, rows 1536.. = WzrhT@W_oo^T
    mm(3 * HD, HD, HD, WzrhT, HD, W_so, HD, PsPoT, HD, nullptr, 0, 0);
    mm(3 * HD, HD, HD, WzrhT, HD, W_oo, HD, PsPoT + (size_t)3 * HD * HD, HD,
       nullptr, 0, 0);

    // --- input projections (numeric path identical to rounds 6/9/10) ---
    k_softmax<<<(NOBJ + 7) / 8, dim3(32, 8)>>>(obj_logit, probs, NOBJ, NO);
    mm(NOBJ, HD, DIM, obj_fmaps, DIM, WobjT, DIM, xo, HD, b_obj, 0, 0);
    {
        dim3 g(HD / 64, NOBJ / 64);
        sgemm_gk<<<g, 256>>>(NOBJ, HD, NO, probs, NO, W_prob, HD, xo, ho, HD,
                             b_prob, 1);     // dual-writes ho = xo
    }

    const int relBlocks4 = (int)(((size_t)NREL * 128 + 255) / 256);
    const int objBlocks  = (int)(((size_t)NOBJ * HD + 255) / 256);

    // --- T GGNN steps ---
    for (int t = 0; t < TSTEP; t++) {
        // Gso = ho @ [PsT | PoT]  (512 x 3072); M small -> keep NW=2 grid
        mm(NOBJ, 6 * HD, HD, ho, HD, PsPoT, HD, Gso, 6 * HD, nullptr, 0, 0);

        k_gather<<<NOBJ, 128>>>(hr, SO);

        // obj GRU (small M -> NW=2)
        mm(NOBJ, HD, 2 * HD, SO, 2 * HD, WrsroT, 2 * HD, mo, HD, nullptr, 0, 0);
        mm2(NOBJ, 2 * HD, 2 * HD, mo, ho, HD, HD, WzrOT, 2 * HD, azrO, 2 * HD,
            nullptr, 0, 0);
        k_obj_zr<<<objBlocks, 256>>>(azrO, bz, br, ho, zO, rhO);
        mm2(NOBJ, HD, 2 * HD, mo, rhO, HD, HD, WhOT, 2 * HD, ahO, HD,
            nullptr, 0, 0);

        // rel GRU (big M -> NW=4 wide tiles, float4 staging)
        mm4(NREL, 2 * HD, HD, hr, HD, UzrT, HD, Azr, 2 * HD, nullptr, 0, 0);
        k_rel_zr<<<relBlocks4, 256>>>(Azr, Gso, hr, rel_inds, bz, br, Zb, RH);
        mm4(NREL, HD, HD, RH, HD, UhT, HD, Ahb, HD, nullptr, 0, 0);
        k_rel_h<<<relBlocks4, 256>>>(Ahb, Gso, Zb, rel_inds, bh, hr);

        k_obj_h<<<objBlocks, 256>>>(ahO, zO, bh, ho);
    }

    // --- relation head (big M -> NW=4) ---
    mm24(NREL, HD, 2 * HD, hr, xr, HD, HD, WorT, 2 * HD, Trel, HD,
         b_out_rel, 0, 1);
    mm(NREL, 128, HD, Trel, HD, WcrT, HD, RC, 128, nullptr, 0, 0);
    k_head<<<(NREL + 7) / 8, dim3(32, 8)>>>(RC, 128, b_cls_rel, NRC, NREL,
                                            dout + O_RELL, dout + O_SCP,
                                            nullptr);

    // --- object head (small M -> NW=2) ---
    mm2(NOBJ, HD, 2 * HD, ho, xo, HD, HD, WobT, 2 * HD, Tobj, HD,
        b_out_obj, 0, 1);
    mm(NOBJ, 256, HD, Tobj, HD, WcoT, HD, OC, 256, nullptr, 0, 0);
    k_head<<<(NOBJ + 7) / 8, dim3(32, 8)>>>(OC, 256, b_cls_obj, NO, NOBJ,
                                            dout + O_OBJREF, dout + O_SCENT,
                                            dout + O_PREDS);
}